// round 16
// baseline (speedup 1.0000x reference)
#include <cuda_runtime.h>
#include <math.h>

#define BATCH 8
#define NPTS  2048
#define HCOLS 1024
#define LOG2E 1.4426950408889634f
#define LN2   0.6931471805599453f
#define TPB   128
#define ROWS_PER_T 2
#define CHUNK 16
#define NMU   12              // MUFU columns per chunk
#define NLU   4               // LUT columns per chunk
#define MAGIC 3072.0f         // 1.5*2^11: dot's last FMA performs range reduction
#define EXPN  4096
#define SH_COLT (HCOLS * 16)
#define SH_BYTES (SH_COLT + EXPN * 4)   // 32 KB

// dual potentials, double-buffered: [buf][s: f_ba,g_ab,f_aa,g_bb][b*NPTS + i]
__device__ float g_dual[2][4][BATCH * NPTS];
// partial sums, double-buffered: [buf][half][s][b*NPTS + r]
__device__ float g_ps[2][2][4][BATCH * NPTS];

__device__ __forceinline__ float ex2(float x) {
    float r; asm("ex2.approx.ftz.f32 %0, %1;" : "=f"(r) : "f"(x)); return r;
}
__device__ __forceinline__ float lg2(float x) {
    float r; asm("lg2.approx.f32 %0, %1;" : "=f"(r) : "f"(x)); return r;
}
__device__ __forceinline__ unsigned long long pk2(float a, float b) {
    unsigned long long u; asm("mov.b64 %0, {%1,%2};" : "=l"(u) : "f"(a), "f"(b)); return u;
}
__device__ __forceinline__ void upk2(unsigned long long u, float& a, float& b) {
    asm("mov.b64 {%0,%1}, %2;" : "=f"(a), "=f"(b) : "l"(u));
}
__device__ __forceinline__ unsigned long long fma2(unsigned long long a,
                                                   unsigned long long b,
                                                   unsigned long long c) {
    unsigned long long d;
    asm("fma.rn.f32x2 %0, %1, %2, %3;" : "=l"(d) : "l"(a), "l"(b), "l"(c));
    return d;
}
__device__ __forceinline__ unsigned long long add2(unsigned long long a,
                                                   unsigned long long b) {
    unsigned long long d;
    asm("add.rn.f32x2 %0, %1, %2;" : "=l"(d) : "l"(a), "l"(b));
    return d;
}

// LUT exp on ALU/FMA pipes. r = arg + 3072 (magic folded into column weight).
// binade [2048,4096): frac = bits&0xFFF (HW round-to-nearest), n = (bits>>12)-283648.
// clamp ib>=283522 -> args < -1024 become scale 2^-126 ~ 0 (exact: they underflow).
__device__ __forceinline__ float lut_acc(const float* __restrict__ etbl,
                                         float r, float acc)
{
    unsigned bits = __float_as_uint(r);
    unsigned fr = bits & 0xFFFu;
    unsigned ib = bits >> 12;
    ib = ib < 283522u ? 283522u : ib;
    float scale = __uint_as_float((ib - 283521u) << 23);
    return fmaf(etbl[fr], scale, acc);
}

// softmin, log2 domain, per-row shift; previous phase's combine fused into the
// prologue (mode 0: first phase; 1: init-combine base=0.5|p|^2; 2: averaged).
__global__ __launch_bounds__(TPB, 4) void sinkhorn_phase(
    const float* __restrict__ x, const float* __restrict__ y,
    float eps, float pcoef, int mode, int rbuf, int wbuf, int psr, int psw)
{
    extern __shared__ char smem_raw[];
    float4* sh = (float4*)smem_raw;
    float* etbl = (float*)(smem_raw + SH_COLT);

    const int s = blockIdx.y;
    const int b = blockIdx.z;
    const int half   = blockIdx.x & 1;
    const int rowblk = blockIdx.x >> 1;
    const float* rows = (s == 0 || s == 2) ? x : y;
    const float* cols = (s == 0 || s == 3) ? y : x;
    const int di = (s == 0) ? 1 : (s == 1) ? 0 : s;

    const float inv_eps = 1.0f / eps;
    const float sc = inv_eps * LOG2E;
    const float logw = -logf((float)NPTS);
    const int col0 = half * HCOLS;

    for (int i = threadIdx.x; i < EXPN; i += TPB)
        etbl[i] = ex2((float)i * (1.0f / EXPN));

    for (int p = threadIdx.x; p < HCOLS / 2; p += TPB) {
        int j = col0 + 2 * p;
        int idx = b * NPTS + j;
        const float* c = cols + idx * 3;
        float c0a = c[0], c1a = c[1], c2a = c[2];
        float c0b = c[3], c1b = c[4], c2b = c[5];
        float sqa = 0.5f * (c0a * c0a + c1a * c1a + c2a * c2a);
        float sqb = 0.5f * (c0b * c0b + c1b * c1b + c2b * c2b);
        float ha = logw, hb = logw;
        if (mode != 0) {
            float pa = g_ps[psr][0][di][idx]     + g_ps[psr][1][di][idx];
            float pb = g_ps[psr][0][di][idx + 1] + g_ps[psr][1][di][idx + 1];
            float base_a = (mode == 1) ? sqa : g_dual[rbuf][di][idx];
            float base_b = (mode == 1) ? sqb : g_dual[rbuf][di][idx + 1];
            ha += (base_a - pcoef * lg2(pa)) * inv_eps;
            hb += (base_b - pcoef * lg2(pb)) * inv_eps;
        }
        float wa = (ha - sqa * inv_eps) * LOG2E;
        float wb = (hb - sqb * inv_eps) * LOG2E;
        if ((p & 7) >= 6) { wa += MAGIC; wb += MAGIC; }   // LUT columns
        sh[2 * p]     = make_float4(c0a * sc, c0b * sc, c1a * sc, c1b * sc);
        sh[2 * p + 1] = make_float4(c2a * sc, c2b * sc, wa, wb);
    }

    // own rows: inline combine -> shift, publish duals for next phase
    const int r0 = rowblk * (TPB * ROWS_PER_T) + threadIdx.x;
    const int r1 = r0 + TPB;
    const int i0 = b * NPTS + r0, i1 = b * NPTS + r1;
    const float* xr0 = rows + i0 * 3;
    const float* xr1 = rows + i1 * 3;
    const float p00 = xr0[0], p01 = xr0[1], p02 = xr0[2];
    const float p10 = xr1[0], p11 = xr1[1], p12 = xr1[2];
    const float sq0 = 0.5f * (p00 * p00 + p01 * p01 + p02 * p02);
    const float sq1 = 0.5f * (p10 * p10 + p11 * p11 + p12 * p12);

    float S0 = 0.0f, S1 = 0.0f;
    if (mode != 0) {
        float pa = g_ps[psr][0][s][i0] + g_ps[psr][1][s][i0];
        float pb = g_ps[psr][0][s][i1] + g_ps[psr][1][s][i1];
        float base0 = (mode == 1) ? sq0 : g_dual[rbuf][s][i0];
        float base1 = (mode == 1) ? sq1 : g_dual[rbuf][s][i1];
        float f0 = base0 - pcoef * lg2(pa);
        float f1 = base1 - pcoef * lg2(pb);
        g_dual[wbuf][s][i0] = f0;
        g_dual[wbuf][s][i1] = f1;
        S0 = (sq0 - f0) * inv_eps * LOG2E;
        S1 = (sq1 - f1) * inv_eps * LOG2E;
    }
    __syncthreads();

    const unsigned long long X00 = pk2(p00, p00), X01 = pk2(p01, p01), X02 = pk2(p02, p02);
    const unsigned long long X10 = pk2(p10, p10), X11 = pk2(p11, p11), X12 = pk2(p12, p12);
    const unsigned long long nS0 = pk2(-S0, -S0), nS1 = pk2(-S1, -S1);

    const ulonglong2* shu = (const ulonglong2*)sh;

    float ssum0 = 0.0f, ssum1 = 0.0f;

    // pipelined state: 12 MUFU args + 4 LUT r-values per row
    float am0[NMU], am1[NMU], lr0[NLU], lr1[NLU];

    // ---- prologue: load + dot chunk 0 ----
    {
        #pragma unroll
        for (int k = 0; k < 8; k++) {
            ulonglong2 A  = shu[2 * k];
            ulonglong2 Bv = shu[2 * k + 1];
            unsigned long long d0 =
                fma2(X00, A.x, fma2(X01, A.y, fma2(X02, Bv.x, add2(Bv.y, nS0))));
            unsigned long long d1 =
                fma2(X10, A.x, fma2(X11, A.y, fma2(X12, Bv.x, add2(Bv.y, nS1))));
            if (k < 6) {
                upk2(d0, am0[2 * k], am0[2 * k + 1]);
                upk2(d1, am1[2 * k], am1[2 * k + 1]);
            } else {
                upk2(d0, lr0[2 * (k - 6)], lr0[2 * (k - 6) + 1]);
                upk2(d1, lr1[2 * (k - 6)], lr1[2 * (k - 6) + 1]);
            }
        }
    }

    #pragma unroll 1
    for (int j = CHUNK; j < HCOLS; j += CHUNK) {
        // (a) next chunk's loads
        ulonglong2 A[8], Bv[8];
        #pragma unroll
        for (int k = 0; k < 8; k++) {
            A[k]  = shu[j + 2 * k];
            Bv[k] = shu[j + 2 * k + 1];
        }

        // (b) current chunk: 24 MUFU exps + 8 LUT exps (idle pipes)
        float e0[NMU], e1[NMU];
        #pragma unroll
        for (int k = 0; k < NMU; k++) e0[k] = ex2(am0[k]);
        #pragma unroll
        for (int k = 0; k < NMU; k++) e1[k] = ex2(am1[k]);
        {
            float t0 = (e0[0] + e0[1]) + (e0[2] + e0[3]);
            float t1 = (e0[4] + e0[5]) + (e0[6] + e0[7]);
            float t2 = (e0[8] + e0[9]) + (e0[10] + e0[11]);
            ssum0 += t0 + (t1 + t2);
            float u0 = (e1[0] + e1[1]) + (e1[2] + e1[3]);
            float u1 = (e1[4] + e1[5]) + (e1[6] + e1[7]);
            float u2 = (e1[8] + e1[9]) + (e1[10] + e1[11]);
            ssum1 += u0 + (u1 + u2);
        }
        #pragma unroll
        for (int k = 0; k < NLU; k++) ssum0 = lut_acc(etbl, lr0[k], ssum0);
        #pragma unroll
        for (int k = 0; k < NLU; k++) ssum1 = lut_acc(etbl, lr1[k], ssum1);

        // (c) dots on arrived data
        #pragma unroll
        for (int k = 0; k < 8; k++) {
            unsigned long long d0 =
                fma2(X00, A[k].x, fma2(X01, A[k].y, fma2(X02, Bv[k].x, add2(Bv[k].y, nS0))));
            unsigned long long d1 =
                fma2(X10, A[k].x, fma2(X11, A[k].y, fma2(X12, Bv[k].x, add2(Bv[k].y, nS1))));
            if (k < 6) {
                upk2(d0, am0[2 * k], am0[2 * k + 1]);
                upk2(d1, am1[2 * k], am1[2 * k + 1]);
            } else {
                upk2(d0, lr0[2 * (k - 6)], lr0[2 * (k - 6) + 1]);
                upk2(d1, lr1[2 * (k - 6)], lr1[2 * (k - 6) + 1]);
            }
        }
    }

    // ---- epilogue: consume last chunk ----
    {
        float e0[NMU], e1[NMU];
        #pragma unroll
        for (int k = 0; k < NMU; k++) e0[k] = ex2(am0[k]);
        #pragma unroll
        for (int k = 0; k < NMU; k++) e1[k] = ex2(am1[k]);
        float t0 = (e0[0] + e0[1]) + (e0[2] + e0[3]);
        float t1 = (e0[4] + e0[5]) + (e0[6] + e0[7]);
        float t2 = (e0[8] + e0[9]) + (e0[10] + e0[11]);
        ssum0 += t0 + (t1 + t2);
        float u0 = (e1[0] + e1[1]) + (e1[2] + e1[3]);
        float u1 = (e1[4] + e1[5]) + (e1[6] + e1[7]);
        float u2 = (e1[8] + e1[9]) + (e1[10] + e1[11]);
        ssum1 += u0 + (u1 + u2);
        #pragma unroll
        for (int k = 0; k < NLU; k++) ssum0 = lut_acc(etbl, lr0[k], ssum0);
        #pragma unroll
        for (int k = 0; k < NLU; k++) ssum1 = lut_acc(etbl, lr1[k], ssum1);
    }

    g_ps[psw][half][s][i0] = ssum0;
    g_ps[psw][half][s][i1] = ssum1;
}

// final combine (no averaging) + divergence reduction
__global__ void sinkhorn_reduce(float* __restrict__ out, int db, int psb, float pcoef)
{
    const int b = blockIdx.x;
    const int tid = threadIdx.x;
    float acc = 0.0f;
    for (int i = tid; i < NPTS; i += 256) {
        int idx = b * NPTS + i;
        float f0 = g_dual[db][0][idx] - pcoef * lg2(g_ps[psb][0][0][idx] + g_ps[psb][1][0][idx]);
        float f1 = g_dual[db][1][idx] - pcoef * lg2(g_ps[psb][0][1][idx] + g_ps[psb][1][1][idx]);
        float f2 = g_dual[db][2][idx] - pcoef * lg2(g_ps[psb][0][2][idx] + g_ps[psb][1][2][idx]);
        float f3 = g_dual[db][3][idx] - pcoef * lg2(g_ps[psb][0][3][idx] + g_ps[psb][1][3][idx]);
        acc += (f0 - f2) + (f1 - f3);
    }
    __shared__ float red[256];
    red[tid] = acc;
    __syncthreads();
    for (int off = 128; off > 0; off >>= 1) {
        if (tid < off) red[tid] += red[tid + off];
        __syncthreads();
    }
    if (tid == 0) out[b] = red[0] * (1.0f / (float)NPTS);
}

extern "C" void kernel_launch(void* const* d_in, const int* in_sizes, int n_in,
                              void* d_out, int out_size)
{
    const float* x = (const float*)d_in[0];
    const float* y = (const float*)d_in[1];
    float* out = (float*)d_out;

    cudaFuncSetAttribute(sinkhorn_phase,
                         cudaFuncAttributeMaxDynamicSharedMemorySize, SH_BYTES);
    cudaFuncSetAttribute(sinkhorn_phase,
                         cudaFuncAttributePreferredSharedMemoryCarveout, 100);

    dim3 grid(2 * NPTS / (TPB * ROWS_PER_T), 4, BATCH);   // 512 blocks

    const float eps_list[8] = {4.0f, 4.0f, 1.0f, 0.25f, 0.0625f,
                               0.015625f, 0.00390625f, 0.0025f};

    // phase 0: init at eps0=4, uniform weights, no shift -> ps[0]
    sinkhorn_phase<<<grid, TPB, SH_BYTES>>>(x, y, 4.0f, 0.0f, 0, 0, 0, 0, 0);
    int ps = 0, db = 0;

    // phase 1: weights from init-combine (base = sq, pcoef = eps0*ln2)
    sinkhorn_phase<<<grid, TPB, SH_BYTES>>>(x, y, eps_list[0], 4.0f * LN2,
                                            1, 0, 0, ps, ps ^ 1);
    ps ^= 1; db = 0;

    // phases 2..8: averaged combine of previous phase
    float prev_eps = eps_list[0];
    for (int i = 1; i < 8; i++) {
        sinkhorn_phase<<<grid, TPB, SH_BYTES>>>(x, y, eps_list[i],
                                                0.5f * prev_eps * LN2,
                                                2, db, db ^ 1, ps, ps ^ 1);
        ps ^= 1; db ^= 1;
        prev_eps = eps_list[i];
    }

    // phase 9: final extrapolation at blur^2
    sinkhorn_phase<<<grid, TPB, SH_BYTES>>>(x, y, 0.0025f,
                                            0.5f * prev_eps * LN2,
                                            2, db, db ^ 1, ps, ps ^ 1);
    ps ^= 1; db ^= 1;

    sinkhorn_reduce<<<BATCH, 256>>>(out, db, ps, 0.0025f * LN2);
}

// round 17
// speedup vs baseline: 1.3784x; 1.3784x over previous
#include <cuda_runtime.h>
#include <math.h>

#define BATCH 8
#define NPTS  2048
#define QCOLS 512             // columns per block (quarter split, load balance)
#define NQ    4
#define LOG2E 1.4426950408889634f
#define LN2   0.6931471805599453f
#define TPB   128
#define ROWS_PER_T 2
#define CHUNK 16
#define SH_BYTES (QCOLS * 16) // 8 KB column table

// dual potentials, double-buffered: [buf][s: f_ba,g_ab,f_aa,g_bb][b*NPTS + i]
__device__ float g_dual[2][4][BATCH * NPTS];
// partial sums, double-buffered: [buf][quarter][s][b*NPTS + r]
__device__ float g_ps[2][NQ][4][BATCH * NPTS];

__device__ __forceinline__ float ex2(float x) {
    float r; asm("ex2.approx.ftz.f32 %0, %1;" : "=f"(r) : "f"(x)); return r;
}
__device__ __forceinline__ float lg2(float x) {
    float r; asm("lg2.approx.f32 %0, %1;" : "=f"(r) : "f"(x)); return r;
}
__device__ __forceinline__ unsigned long long pk2(float a, float b) {
    unsigned long long u; asm("mov.b64 %0, {%1,%2};" : "=l"(u) : "f"(a), "f"(b)); return u;
}
__device__ __forceinline__ void upk2(unsigned long long u, float& a, float& b) {
    asm("mov.b64 {%0,%1}, %2;" : "=f"(a), "=f"(b) : "l"(u));
}
__device__ __forceinline__ unsigned long long fma2(unsigned long long a,
                                                   unsigned long long b,
                                                   unsigned long long c) {
    unsigned long long d;
    asm("fma.rn.f32x2 %0, %1, %2, %3;" : "=l"(d) : "l"(a), "l"(b), "l"(c));
    return d;
}
__device__ __forceinline__ unsigned long long add2(unsigned long long a,
                                                   unsigned long long b) {
    unsigned long long d;
    asm("add.rn.f32x2 %0, %1, %2;" : "=l"(d) : "l"(a), "l"(b));
    return d;
}

__device__ __forceinline__ float ps4(int buf, int s, int idx) {
    return (g_ps[buf][0][s][idx] + g_ps[buf][1][s][idx])
         + (g_ps[buf][2][s][idx] + g_ps[buf][3][s][idx]);
}

// softmin, log2 domain, per-row shift; previous phase's combine fused into the
// prologue (mode 0: first phase; 1: init-combine base=0.5|p|^2; 2: averaged).
// f_prev = base - pcoef * log2(sum of 4 quarter partials).
__global__ __launch_bounds__(TPB, 4) void sinkhorn_phase(
    const float* __restrict__ x, const float* __restrict__ y,
    float eps, float pcoef, int mode, int rbuf, int wbuf, int psr, int psw)
{
    extern __shared__ float4 sh[];

    const int s = blockIdx.y;
    const int b = blockIdx.z;
    const int q      = blockIdx.x & 3;
    const int rowblk = blockIdx.x >> 2;          // 0..7, 256 rows each
    const float* rows = (s == 0 || s == 2) ? x : y;
    const float* cols = (s == 0 || s == 3) ? y : x;
    const int di = (s == 0) ? 1 : (s == 1) ? 0 : s;

    const float inv_eps = 1.0f / eps;
    const float sc = inv_eps * LOG2E;
    const float logw = -logf((float)NPTS);
    const int col0 = q * QCOLS;

    // column table with inline previous combine
    for (int p = threadIdx.x; p < QCOLS / 2; p += TPB) {
        int j = col0 + 2 * p;
        int idx = b * NPTS + j;
        const float* c = cols + idx * 3;
        float c0a = c[0], c1a = c[1], c2a = c[2];
        float c0b = c[3], c1b = c[4], c2b = c[5];
        float sqa = 0.5f * (c0a * c0a + c1a * c1a + c2a * c2a);
        float sqb = 0.5f * (c0b * c0b + c1b * c1b + c2b * c2b);
        float ha = logw, hb = logw;
        if (mode != 0) {
            float pa = ps4(psr, di, idx);
            float pb = ps4(psr, di, idx + 1);
            float base_a = (mode == 1) ? sqa : g_dual[rbuf][di][idx];
            float base_b = (mode == 1) ? sqb : g_dual[rbuf][di][idx + 1];
            ha += (base_a - pcoef * lg2(pa)) * inv_eps;
            hb += (base_b - pcoef * lg2(pb)) * inv_eps;
        }
        float wa = (ha - sqa * inv_eps) * LOG2E;
        float wb = (hb - sqb * inv_eps) * LOG2E;
        sh[2 * p]     = make_float4(c0a * sc, c0b * sc, c1a * sc, c1b * sc);
        sh[2 * p + 1] = make_float4(c2a * sc, c2b * sc, wa, wb);
    }

    // own rows: inline combine -> shift, publish duals for next phase
    const int r0 = rowblk * (TPB * ROWS_PER_T) + threadIdx.x;
    const int r1 = r0 + TPB;
    const int i0 = b * NPTS + r0, i1 = b * NPTS + r1;
    const float* xr0 = rows + i0 * 3;
    const float* xr1 = rows + i1 * 3;
    const float p00 = xr0[0], p01 = xr0[1], p02 = xr0[2];
    const float p10 = xr1[0], p11 = xr1[1], p12 = xr1[2];
    const float sq0 = 0.5f * (p00 * p00 + p01 * p01 + p02 * p02);
    const float sq1 = 0.5f * (p10 * p10 + p11 * p11 + p12 * p12);

    float S0 = 0.0f, S1 = 0.0f;
    if (mode != 0) {
        float pa = ps4(psr, s, i0);
        float pb = ps4(psr, s, i1);
        float base0 = (mode == 1) ? sq0 : g_dual[rbuf][s][i0];
        float base1 = (mode == 1) ? sq1 : g_dual[rbuf][s][i1];
        float f0 = base0 - pcoef * lg2(pa);
        float f1 = base1 - pcoef * lg2(pb);
        g_dual[wbuf][s][i0] = f0;   // all quarters write identical values: benign
        g_dual[wbuf][s][i1] = f1;
        S0 = (sq0 - f0) * inv_eps * LOG2E;
        S1 = (sq1 - f1) * inv_eps * LOG2E;
    }
    __syncthreads();

    const unsigned long long X00 = pk2(p00, p00), X01 = pk2(p01, p01), X02 = pk2(p02, p02);
    const unsigned long long X10 = pk2(p10, p10), X11 = pk2(p11, p11), X12 = pk2(p12, p12);
    const unsigned long long nS0 = pk2(-S0, -S0), nS1 = pk2(-S1, -S1);

    const ulonglong2* shu = (const ulonglong2*)sh;

    float ssum0 = 0.0f, ssum1 = 0.0f;

    // ---- prologue: load + dot chunk 0 (both rows) ----
    float a0[CHUNK], a1[CHUNK];
    {
        #pragma unroll
        for (int k = 0; k < CHUNK / 2; k++) {
            ulonglong2 A  = shu[2 * k];
            ulonglong2 Bv = shu[2 * k + 1];
            unsigned long long d0 =
                fma2(X00, A.x, fma2(X01, A.y, fma2(X02, Bv.x, add2(Bv.y, nS0))));
            unsigned long long d1 =
                fma2(X10, A.x, fma2(X11, A.y, fma2(X12, Bv.x, add2(Bv.y, nS1))));
            upk2(d0, a0[2 * k], a0[2 * k + 1]);
            upk2(d1, a1[2 * k], a1[2 * k + 1]);
        }
    }

    #pragma unroll 1
    for (int j = CHUNK; j < QCOLS; j += CHUNK) {
        // (a) next chunk's loads
        ulonglong2 A[CHUNK / 2], Bv[CHUNK / 2];
        #pragma unroll
        for (int k = 0; k < CHUNK / 2; k++) {
            A[k]  = shu[j + 2 * k];
            Bv[k] = shu[j + 2 * k + 1];
        }

        // (b) current chunk's exps + sums, both rows (MUFU saturating)
        float e0[CHUNK], e1[CHUNK];
        #pragma unroll
        for (int k = 0; k < CHUNK; k++) e0[k] = ex2(a0[k]);
        #pragma unroll
        for (int k = 0; k < CHUNK; k++) e1[k] = ex2(a1[k]);
        {
            float t0 = (e0[0] + e0[1]) + (e0[2] + e0[3]);
            float t1 = (e0[4] + e0[5]) + (e0[6] + e0[7]);
            float t2 = (e0[8] + e0[9]) + (e0[10] + e0[11]);
            float t3 = (e0[12] + e0[13]) + (e0[14] + e0[15]);
            ssum0 += (t0 + t1) + (t2 + t3);
            float u0 = (e1[0] + e1[1]) + (e1[2] + e1[3]);
            float u1 = (e1[4] + e1[5]) + (e1[6] + e1[7]);
            float u2 = (e1[8] + e1[9]) + (e1[10] + e1[11]);
            float u3 = (e1[12] + e1[13]) + (e1[14] + e1[15]);
            ssum1 += (u0 + u1) + (u2 + u3);
        }

        // (c) dots on arrived data
        #pragma unroll
        for (int k = 0; k < CHUNK / 2; k++) {
            unsigned long long d0 =
                fma2(X00, A[k].x, fma2(X01, A[k].y, fma2(X02, Bv[k].x, add2(Bv[k].y, nS0))));
            unsigned long long d1 =
                fma2(X10, A[k].x, fma2(X11, A[k].y, fma2(X12, Bv[k].x, add2(Bv[k].y, nS1))));
            upk2(d0, a0[2 * k], a0[2 * k + 1]);
            upk2(d1, a1[2 * k], a1[2 * k + 1]);
        }
    }

    // ---- epilogue: consume last chunk ----
    {
        float e0[CHUNK], e1[CHUNK];
        #pragma unroll
        for (int k = 0; k < CHUNK; k++) e0[k] = ex2(a0[k]);
        #pragma unroll
        for (int k = 0; k < CHUNK; k++) e1[k] = ex2(a1[k]);
        float t0 = (e0[0] + e0[1]) + (e0[2] + e0[3]);
        float t1 = (e0[4] + e0[5]) + (e0[6] + e0[7]);
        float t2 = (e0[8] + e0[9]) + (e0[10] + e0[11]);
        float t3 = (e0[12] + e0[13]) + (e0[14] + e0[15]);
        ssum0 += (t0 + t1) + (t2 + t3);
        float u0 = (e1[0] + e1[1]) + (e1[2] + e1[3]);
        float u1 = (e1[4] + e1[5]) + (e1[6] + e1[7]);
        float u2 = (e1[8] + e1[9]) + (e1[10] + e1[11]);
        float u3 = (e1[12] + e1[13]) + (e1[14] + e1[15]);
        ssum1 += (u0 + u1) + (u2 + u3);
    }

    g_ps[psw][q][s][i0] = ssum0;
    g_ps[psw][q][s][i1] = ssum1;
}

// final combine (no averaging) + divergence reduction
__global__ void sinkhorn_reduce(float* __restrict__ out, int db, int psb, float pcoef)
{
    const int b = blockIdx.x;
    const int tid = threadIdx.x;
    float acc = 0.0f;
    for (int i = tid; i < NPTS; i += 256) {
        int idx = b * NPTS + i;
        float f0 = g_dual[db][0][idx] - pcoef * lg2(ps4(psb, 0, idx));
        float f1 = g_dual[db][1][idx] - pcoef * lg2(ps4(psb, 1, idx));
        float f2 = g_dual[db][2][idx] - pcoef * lg2(ps4(psb, 2, idx));
        float f3 = g_dual[db][3][idx] - pcoef * lg2(ps4(psb, 3, idx));
        acc += (f0 - f2) + (f1 - f3);
    }
    __shared__ float red[256];
    red[tid] = acc;
    __syncthreads();
    for (int off = 128; off > 0; off >>= 1) {
        if (tid < off) red[tid] += red[tid + off];
        __syncthreads();
    }
    if (tid == 0) out[b] = red[0] * (1.0f / (float)NPTS);
}

extern "C" void kernel_launch(void* const* d_in, const int* in_sizes, int n_in,
                              void* d_out, int out_size)
{
    const float* x = (const float*)d_in[0];
    const float* y = (const float*)d_in[1];
    float* out = (float*)d_out;

    cudaFuncSetAttribute(sinkhorn_phase,
                         cudaFuncAttributeMaxDynamicSharedMemorySize, SH_BYTES);
    cudaFuncSetAttribute(sinkhorn_phase,
                         cudaFuncAttributePreferredSharedMemoryCarveout, 100);

    // 8 rowblks x 4 quarters, 4 softmins, 8 batches = 1024 blocks (6.92/SM)
    dim3 grid(NQ * NPTS / (TPB * ROWS_PER_T), 4, BATCH);

    const float eps_list[8] = {4.0f, 4.0f, 1.0f, 0.25f, 0.0625f,
                               0.015625f, 0.00390625f, 0.0025f};

    // phase 0: init at eps0=4, uniform weights, no shift -> ps[0]
    sinkhorn_phase<<<grid, TPB, SH_BYTES>>>(x, y, 4.0f, 0.0f, 0, 0, 0, 0, 0);
    int ps = 0, db = 0;

    // phase 1: weights from init-combine (base = sq, pcoef = eps0*ln2)
    sinkhorn_phase<<<grid, TPB, SH_BYTES>>>(x, y, eps_list[0], 4.0f * LN2,
                                            1, 0, 0, ps, ps ^ 1);
    ps ^= 1; db = 0;

    // phases 2..8: averaged combine of previous phase
    float prev_eps = eps_list[0];
    for (int i = 1; i < 8; i++) {
        sinkhorn_phase<<<grid, TPB, SH_BYTES>>>(x, y, eps_list[i],
                                                0.5f * prev_eps * LN2,
                                                2, db, db ^ 1, ps, ps ^ 1);
        ps ^= 1; db ^= 1;
        prev_eps = eps_list[i];
    }

    // phase 9: final extrapolation at blur^2
    sinkhorn_phase<<<grid, TPB, SH_BYTES>>>(x, y, 0.0025f,
                                            0.5f * prev_eps * LN2,
                                            2, db, db ^ 1, ps, ps ^ 1);
    ps ^= 1; db ^= 1;

    sinkhorn_reduce<<<BATCH, 256>>>(out, db, ps, 0.0025f * LN2);
}